// round 11
// baseline (speedup 1.0000x reference)
#include <cuda_runtime.h>
#include <stdint.h>

#define Ss 2048
#define Dh 256

__device__ __align__(16) unsigned char g_qimg[8 * 64 * 32768];  // A-frag images, 32-row q-tiles
__device__ __align__(16) unsigned char g_kimg[8 * 64 * 32768];  // B-frag images, 32-key tiles
__device__ __align__(16) unsigned char g_eimg[8 * 64 * 32768];  // B-frag images, 32-key tiles
__device__ __align__(16) unsigned char g_wimg[8 * 32768];       // B-frag images, 32-j chunks

// ---------------- helpers ----------------
__device__ __forceinline__ uint32_t smem_u32(const void* p) {
    uint32_t a; asm("{.reg .u64 t; cvta.to.shared.u64 t,%1; cvt.u32.u64 %0,t;}" : "=r"(a) : "l"(p)); return a;
}
__device__ __forceinline__ uint32_t tf32r(float x) {
    uint32_t r; asm("cvt.rna.tf32.f32 %0,%1;" : "=r"(r) : "f"(x)); return r;
}
__device__ __forceinline__ void mmat(float* c, const uint32_t* a, const uint32_t* b) {
    asm volatile("mma.sync.aligned.m16n8k8.row.col.f32.tf32.tf32.f32 "
        "{%0,%1,%2,%3},{%4,%5,%6,%7},{%8,%9},{%0,%1,%2,%3};"
        : "+f"(c[0]), "+f"(c[1]), "+f"(c[2]), "+f"(c[3])
        : "r"(a[0]), "r"(a[1]), "r"(a[2]), "r"(a[3]), "r"(b[0]), "r"(b[1]));
}
__device__ __forceinline__ float expclip(float s) {
    return __expf(fminf(fmaxf(s * 0.0625f, -10.f), 10.f));
}
__device__ __forceinline__ void cpa16(uint32_t dst, const void* src) {
    asm volatile("cp.async.cg.shared.global [%0],[%1],16;" :: "r"(dst), "l"(src));
}
#define CP_COMMIT() asm volatile("cp.async.commit_group;" ::: "memory")
#define CP_WAIT1()  asm volatile("cp.async.wait_group 1;" ::: "memory")

__device__ __forceinline__ void load32k(uint32_t dst, const unsigned char* src, int tid) {
#pragma unroll
    for (int i = 0; i < 8; i++)
        cpa16(dst + (uint32_t)(tid + 256 * i) * 16, src + (size_t)(tid + 256 * i) * 16);
}

// ---------------- prologue kernels ----------------
// z=0: Q A-frag image; z=1: K B-frag image; z=2: E B-frag image
__global__ void img_kernel(const float* __restrict__ p, const float* __restrict__ e) {
    int t = blockIdx.x, b = blockIdx.y, z = blockIdx.z, tid = threadIdx.x;
    if (z == 0) {
        const float* P = p + (size_t)b * (Ss + 1) * Dh;
        uint4* dst = (uint4*)(g_qimg + (size_t)(b * 64 + t) * 32768);
#pragma unroll
        for (int it = 0; it < 8; it++) {
            int idx = tid + 256 * it;
            int mblk = idx >> 10, rem = idx & 1023, s = rem >> 5, l = rem & 31;
            int r = t * 32 + mblk * 16 + (l >> 2) + 1;   // +1: q = p[:,1:,:]
            int c = 8 * s + (l & 3);
            uint4 v;
            v.x = tf32r(P[(size_t)r * Dh + c]);
            v.y = tf32r(P[(size_t)(r + 8) * Dh + c]);
            v.z = tf32r(P[(size_t)r * Dh + c + 4]);
            v.w = tf32r(P[(size_t)(r + 8) * Dh + c + 4]);
            dst[idx] = v;
        }
    } else if (z == 1) {
        const float* P = p + (size_t)b * (Ss + 1) * Dh;
        uint2* dst = (uint2*)(g_kimg + (size_t)(b * 64 + t) * 32768);
#pragma unroll
        for (int it = 0; it < 16; it++) {
            int idx = tid + 256 * it;
            int s = idx >> 7, rem = idx & 127, nt = rem >> 5, l = rem & 31;
            int key = t * 32 + nt * 8 + (l >> 2);
            int d = 8 * s + (l & 3);
            dst[idx] = make_uint2(tf32r(P[(size_t)key * Dh + d]), tf32r(P[(size_t)key * Dh + d + 4]));
        }
    } else {
        const float* E = e + (size_t)b * Ss * Dh;
        uint2* dst = (uint2*)(g_eimg + (size_t)(b * 64 + t) * 32768);
#pragma unroll
        for (int it = 0; it < 16; it++) {
            int idx = tid + 256 * it;
            int s = idx >> 10, rem = idx & 1023, nt = rem >> 5, l = rem & 31;
            int key = t * 32 + 8 * s + (l & 3);
            int n = nt * 8 + (l >> 2);
            dst[idx] = make_uint2(tf32r(E[(size_t)key * Dh + n]), tf32r(E[(size_t)(key + 4) * Dh + n]));
        }
    }
}
// W image straight from W_o (fold 8 heads inline): element (j, n=dout)
__global__ void wimg_kernel(const float* __restrict__ W_o) {
    int ch = blockIdx.x, tid = threadIdx.x;
    uint2* dst = (uint2*)(g_wimg + (size_t)ch * 32768);
#pragma unroll
    for (int it = 0; it < 16; it++) {
        int idx = tid + 256 * it;
        int s = idx >> 10, rem = idx & 1023, nt = rem >> 5, l = rem & 31;
        int j = 32 * ch + 8 * s + (l & 3);
        int n = nt * 8 + (l >> 2);
        float s0 = 0.f, s1 = 0.f;
#pragma unroll
        for (int h = 0; h < 8; h++) {
            s0 += W_o[(size_t)n * 2048 + h * 256 + j];
            s1 += W_o[(size_t)n * 2048 + h * 256 + j + 4];
        }
        dst[idx] = make_uint2(tf32r(s0), tf32r(s1));
    }
}

// ---------------- main kernel ----------------
// smem layout (bytes); ynorm [32][260] f32 (33280) overlays SQ+SP after the loop
#define SQ   0u        // Q image, 32768
#define SP   32768u    // P [32 rows][36 f32] = 4608
#define SK   37376u    // K tile image, 32768
#define SE   70144u    // E tile image, 32768
#define SDEN 102912u   // [4][32] f32
#define SMEM_BYTES 103424u

__global__ __launch_bounds__(256, 2) void attn_kernel(float* __restrict__ out) {
    extern __shared__ unsigned char smp[];
    const uint32_t sb = smem_u32(smp);
    const int tid = threadIdx.x, w = tid >> 5, l = tid & 31;
    const int tig = l & 3, gid = l >> 2;
    const int qt = 63 - (int)blockIdx.x, b = blockIdx.y;
    const int q0 = qt * 32, cnt = qt + 1;
    const int mblk = w & 1, hq = w >> 1;   // row half, col quarter

    const unsigned char* kim = g_kimg + (size_t)(b * 64) * 32768;
    const unsigned char* eim = g_eimg + (size_t)(b * 64) * 32768;

    // prologue loads: [Q + K0], [E0]
    load32k(sb + SQ, g_qimg + (size_t)(b * 64 + qt) * 32768, tid);
    load32k(sb + SK, kim, tid);
    CP_COMMIT();
    load32k(sb + SE, eim, tid);
    CP_COMMIT();

    // per-warp address bases
    const uint32_t qbase = (uint32_t)(mblk * 16384) + l * 16;      // + s*512
    const uint32_t kfq = (uint32_t)hq * 256 + l * 8;               // + s*1024
    const uint32_t prow = (uint32_t)(mblk * 16 + gid);
    const uint32_t pbase = SP + (prow * 36 + tig) * 4;             // + 8s*4
    const uint32_t efoff = (uint32_t)(8 * hq) * 256 + l * 8;       // + s*8192 + ntl*256

    float yacc[8][4];
#pragma unroll
    for (int nt = 0; nt < 8; nt++)
#pragma unroll
        for (int j = 0; j < 4; j++) yacc[nt][j] = 0.f;
    float d0 = 0.f, d1 = 0.f;

    for (int t = 0; t < cnt; t++) {
        CP_WAIT1();                 // Q + K_t resident (E_t may be in flight)
        __syncthreads();

        // ---- S = Q K^T : warp -> S[16 rows @ 16mblk][8 cols @ 8hq] ----
        float sacc[4];
        sacc[0] = sacc[1] = sacc[2] = sacc[3] = 0.f;
#pragma unroll 8
        for (int s = 0; s < 32; s++) {
            uint32_t qa[4], kf[2];
            *(uint4*)qa = *(const uint4*)(smp + SQ + qbase + (uint32_t)s * 512);
            *(uint2*)kf = *(const uint2*)(smp + SK + (uint32_t)s * 1024 + kfq);
            mmat(sacc, qa, kf);
        }
        __syncthreads();            // K buffer readers done
        if (t + 1 < cnt) load32k(sb + SK, kim + (size_t)(t + 1) * 32768, tid);
        CP_COMMIT();                // K_{t+1} (or empty) -- overlaps exp + AV

        // ---- exp/mask -> tf32 P (smem) + den ----
        {
            const int r0 = q0 + mblk * 16 + gid, r1 = r0 + 8;
            const int c0 = t * 32 + 8 * hq + 2 * tig, c1 = c0 + 1;
            uint32_t t00, t01, t10, t11;
            if (t == cnt - 1) {     // diagonal tile: apply causal mask
                t00 = tf32r((c0 <= r0) ? expclip(sacc[0]) : 0.f);
                t01 = tf32r((c1 <= r0) ? expclip(sacc[1]) : 0.f);
                t10 = tf32r((c0 <= r1) ? expclip(sacc[2]) : 0.f);
                t11 = tf32r((c1 <= r1) ? expclip(sacc[3]) : 0.f);
            } else {
                t00 = tf32r(expclip(sacc[0]));
                t01 = tf32r(expclip(sacc[1]));
                t10 = tf32r(expclip(sacc[2]));
                t11 = tf32r(expclip(sacc[3]));
            }
            d0 += __uint_as_float(t00) + __uint_as_float(t01);
            d1 += __uint_as_float(t10) + __uint_as_float(t11);
            uint32_t a = SP + (prow * 36 + 8 * hq + 2 * tig) * 4;
            *(uint2*)(smp + a) = make_uint2(t00, t01);
            *(uint2*)(smp + a + 8 * 36 * 4) = make_uint2(t10, t11);
        }
        CP_WAIT1();                 // E_t resident (K_{t+1} still in flight)
        __syncthreads();            // P visible

        // ---- y += P E : warp -> y[16 rows][64 cols @ 64hq] ----
#pragma unroll
        for (int s = 0; s < 4; s++) {
            uint32_t pa[4];
            uint32_t pb = pbase + (uint32_t)(8 * s) * 4;
            pa[0] = *(const uint32_t*)(smp + pb);
            pa[1] = *(const uint32_t*)(smp + pb + 8 * 36 * 4);
            pa[2] = *(const uint32_t*)(smp + pb + 16);
            pa[3] = *(const uint32_t*)(smp + pb + 8 * 36 * 4 + 16);
#pragma unroll
            for (int ntl = 0; ntl < 8; ntl++) {
                uint32_t ef[2];
                *(uint2*)ef = *(const uint2*)(smp + SE + (uint32_t)s * 8192 + efoff + ntl * 256);
                mmat(yacc[ntl], pa, ef);
            }
        }
        __syncthreads();            // E buffer readers done
        if (t + 1 < cnt) load32k(sb + SE, eim + (size_t)(t + 1) * 32768, tid);
        CP_COMMIT();                // E_{t+1} (or empty) -- overlaps next QK
    }

    // ---- den reduce (4 col-quarters) ----
    d0 += __shfl_xor_sync(~0u, d0, 1); d0 += __shfl_xor_sync(~0u, d0, 2);
    d1 += __shfl_xor_sync(~0u, d1, 1); d1 += __shfl_xor_sync(~0u, d1, 2);
    if (tig == 0) {
        *(float*)(smp + SDEN + (hq * 32 + mblk * 16 + gid) * 4) = d0;
        *(float*)(smp + SDEN + (hq * 32 + mblk * 16 + gid + 8) * 4) = d1;
    }
    __syncthreads();
    float inv0, inv1;
    {
        const float* dn = (const float*)(smp + SDEN);
        int r = mblk * 16 + gid;
        float s0 = dn[r] + dn[32 + r] + dn[64 + r] + dn[96 + r];
        float s1 = dn[r + 8] + dn[32 + r + 8] + dn[64 + r + 8] + dn[96 + r + 8];
        inv0 = 1.f / (s0 * (float)(q0 + r + 1));
        inv1 = 1.f / (s1 * (float)(q0 + r + 9));
    }

    // start W pipeline into freed K/E buffers
    load32k(sb + SK, g_wimg, tid); CP_COMMIT();
    load32k(sb + SE, g_wimg + 32768, tid); CP_COMMIT();

    // ---- stage ynorm (tf32) into [32][260] over SQ+SP ----
#pragma unroll
    for (int ntl = 0; ntl < 8; ntl++) {
        uint32_t col = 64 * hq + 8 * ntl + 2 * tig;
        uint32_t a = (prow * 260 + col) * 4;
        *(uint2*)(smp + a) = make_uint2(tf32r(yacc[ntl][0] * inv0), tf32r(yacc[ntl][1] * inv0));
        *(uint2*)(smp + a + 8 * 260 * 4) = make_uint2(tf32r(yacc[ntl][2] * inv1), tf32r(yacc[ntl][3] * inv1));
#pragma unroll
        for (int j = 0; j < 4; j++) yacc[ntl][j] = 0.f;
    }
    __syncthreads();                // ynorm visible

    // ---- epilogue: out = ynorm @ W2 (8 chunks of 32 j) ----
#pragma unroll 1
    for (int c = 0; c < 8; c++) {
        CP_WAIT1();
        __syncthreads();
        const uint32_t wb = (c & 1) ? SE : SK;
#pragma unroll
        for (int s = 0; s < 4; s++) {
            uint32_t ya[4];
            uint32_t yb = (prow * 260 + 32 * c + 8 * s + tig) * 4;
            ya[0] = *(const uint32_t*)(smp + yb);
            ya[1] = *(const uint32_t*)(smp + yb + 8 * 260 * 4);
            ya[2] = *(const uint32_t*)(smp + yb + 16);
            ya[3] = *(const uint32_t*)(smp + yb + 8 * 260 * 4 + 16);
#pragma unroll
            for (int ntl = 0; ntl < 8; ntl++) {
                uint32_t wf[2];
                *(uint2*)wf = *(const uint2*)(smp + wb + (uint32_t)s * 8192 + efoff + ntl * 256);
                mmat(yacc[ntl], ya, wf);
            }
        }
        __syncthreads();            // buffer readers done
        if (c + 2 < 8) load32k(sb + ((c & 1) ? SE : SK), g_wimg + (size_t)(c + 2) * 32768, tid);
        CP_COMMIT();                // real or empty group
    }

    // ---- store ----
    {
        const int orow = q0 + mblk * 16 + gid;
        float* ob = out + ((size_t)b * Ss + orow) * Dh;
#pragma unroll
        for (int ntl = 0; ntl < 8; ntl++) {
            int col = 64 * hq + 8 * ntl + 2 * tig;
            *(float2*)(ob + col) = make_float2(yacc[ntl][0], yacc[ntl][1]);
            *(float2*)(ob + 8 * Dh + col) = make_float2(yacc[ntl][2], yacc[ntl][3]);
        }
    }
}

extern "C" void kernel_launch(void* const* d_in, const int* in_sizes, int n_in,
                              void* d_out, int out_size) {
    const float* e   = (const float*)d_in[0];
    const float* p   = (const float*)d_in[1];
    const float* W_o = (const float*)d_in[2];
    float* out = (float*)d_out;

    cudaFuncSetAttribute(attn_kernel, cudaFuncAttributeMaxDynamicSharedMemorySize, SMEM_BYTES);

    img_kernel<<<dim3(64, 8, 3), 256>>>(p, e);
    wimg_kernel<<<8, 256>>>(W_o);
    attn_kernel<<<dim3(64, 8), 256, SMEM_BYTES>>>(out);
}

// round 12
// speedup vs baseline: 1.2148x; 1.2148x over previous
#include <cuda_runtime.h>
#include <stdint.h>

#define Ss 2048
#define Dh 256

__device__ __align__(16) unsigned char g_qimg[8 * 64 * 32768];  // A-frag images, 32-row q-tiles
__device__ __align__(16) unsigned char g_kimg[8 * 64 * 32768];  // B-frag images, 32-key tiles
__device__ __align__(16) unsigned char g_eimg[8 * 64 * 32768];  // B-frag images, 32-key tiles
__device__ __align__(16) unsigned char g_wimg[8 * 32768];       // B-frag images, 32-j chunks

// ---------------- helpers ----------------
__device__ __forceinline__ uint32_t smem_u32(const void* p) {
    uint32_t a; asm("{.reg .u64 t; cvta.to.shared.u64 t,%1; cvt.u32.u64 %0,t;}" : "=r"(a) : "l"(p)); return a;
}
__device__ __forceinline__ uint32_t tf32r(float x) {
    uint32_t r; asm("cvt.rna.tf32.f32 %0,%1;" : "=r"(r) : "f"(x)); return r;
}
__device__ __forceinline__ void mmat(float* c, const uint32_t* a, const uint32_t* b) {
    asm volatile("mma.sync.aligned.m16n8k8.row.col.f32.tf32.tf32.f32 "
        "{%0,%1,%2,%3},{%4,%5,%6,%7},{%8,%9},{%0,%1,%2,%3};"
        : "+f"(c[0]), "+f"(c[1]), "+f"(c[2]), "+f"(c[3])
        : "r"(a[0]), "r"(a[1]), "r"(a[2]), "r"(a[3]), "r"(b[0]), "r"(b[1]));
}
__device__ __forceinline__ float expclip(float s) {
    return __expf(fminf(fmaxf(s * 0.0625f, -10.f), 10.f));
}
__device__ __forceinline__ void cpa16(uint32_t dst, const void* src) {
    asm volatile("cp.async.cg.shared.global [%0],[%1],16;" :: "r"(dst), "l"(src));
}
#define CP_COMMIT() asm volatile("cp.async.commit_group;" ::: "memory")
#define CP_WAIT1()  asm volatile("cp.async.wait_group 1;" ::: "memory")

__device__ __forceinline__ void load32k(uint32_t dst, const unsigned char* src, int tid) {
#pragma unroll
    for (int i = 0; i < 16; i++)
        cpa16(dst + (uint32_t)(tid + 128 * i) * 16, src + (size_t)(tid + 128 * i) * 16);
}

// ---------------- prologue kernels ----------------
// z=0: Q A-frag image; z=1: K B-frag image; z=2: E B-frag image
__global__ void img_kernel(const float* __restrict__ p, const float* __restrict__ e) {
    int t = blockIdx.x, b = blockIdx.y, z = blockIdx.z, tid = threadIdx.x;
    if (z == 0) {
        const float* P = p + (size_t)b * (Ss + 1) * Dh;
        uint4* dst = (uint4*)(g_qimg + (size_t)(b * 64 + t) * 32768);
#pragma unroll
        for (int it = 0; it < 8; it++) {
            int idx = tid + 256 * it;
            int mblk = idx >> 10, rem = idx & 1023, s = rem >> 5, l = rem & 31;
            int r = t * 32 + mblk * 16 + (l >> 2) + 1;   // +1: q = p[:,1:,:]
            int c = 8 * s + (l & 3);
            uint4 v;
            v.x = tf32r(P[(size_t)r * Dh + c]);
            v.y = tf32r(P[(size_t)(r + 8) * Dh + c]);
            v.z = tf32r(P[(size_t)r * Dh + c + 4]);
            v.w = tf32r(P[(size_t)(r + 8) * Dh + c + 4]);
            dst[idx] = v;
        }
    } else if (z == 1) {
        const float* P = p + (size_t)b * (Ss + 1) * Dh;
        uint2* dst = (uint2*)(g_kimg + (size_t)(b * 64 + t) * 32768);
#pragma unroll
        for (int it = 0; it < 16; it++) {
            int idx = tid + 256 * it;
            int s = idx >> 7, rem = idx & 127, nt = rem >> 5, l = rem & 31;
            int key = t * 32 + nt * 8 + (l >> 2);
            int d = 8 * s + (l & 3);
            dst[idx] = make_uint2(tf32r(P[(size_t)key * Dh + d]), tf32r(P[(size_t)key * Dh + d + 4]));
        }
    } else {
        const float* E = e + (size_t)b * Ss * Dh;
        uint2* dst = (uint2*)(g_eimg + (size_t)(b * 64 + t) * 32768);
#pragma unroll
        for (int it = 0; it < 16; it++) {
            int idx = tid + 256 * it;
            int s = idx >> 10, rem = idx & 1023, nt = rem >> 5, l = rem & 31;
            int key = t * 32 + 8 * s + (l & 3);
            int n = nt * 8 + (l >> 2);
            dst[idx] = make_uint2(tf32r(E[(size_t)key * Dh + n]), tf32r(E[(size_t)(key + 4) * Dh + n]));
        }
    }
}
// W image straight from W_o (fold 8 heads inline): element (j, n=dout)
__global__ void wimg_kernel(const float* __restrict__ W_o) {
    int ch = blockIdx.x, tid = threadIdx.x;
    uint2* dst = (uint2*)(g_wimg + (size_t)ch * 32768);
#pragma unroll
    for (int it = 0; it < 16; it++) {
        int idx = tid + 256 * it;
        int s = idx >> 10, rem = idx & 1023, nt = rem >> 5, l = rem & 31;
        int j = 32 * ch + 8 * s + (l & 3);
        int n = nt * 8 + (l >> 2);
        float s0 = 0.f, s1 = 0.f;
#pragma unroll
        for (int h = 0; h < 8; h++) {
            s0 += W_o[(size_t)n * 2048 + h * 256 + j];
            s1 += W_o[(size_t)n * 2048 + h * 256 + j + 4];
        }
        dst[idx] = make_uint2(tf32r(s0), tf32r(s1));
    }
}

// ---------------- main kernel ----------------
// smem layout (bytes); ynorm [32][260] f32 (33280) overlays SQ+SP after the loop
#define SQ   0u        // Q image, 32768
#define SP   32768u    // P [32 rows][36 f32] = 4608
#define SK   37376u    // K tile image, 32768
#define SE   70144u    // E tile image, 32768
#define SDEN 102912u   // [2][32] f32
#define SMEM_BYTES 103168u

__global__ __launch_bounds__(128, 2) void attn_kernel(float* __restrict__ out) {
    extern __shared__ unsigned char smp[];
    const uint32_t sb = smem_u32(smp);
    const int tid = threadIdx.x, w = tid >> 5, l = tid & 31;
    const int tig = l & 3, gid = l >> 2;
    const int qt = 63 - (int)blockIdx.x, b = blockIdx.y;
    const int q0 = qt * 32, cnt = qt + 1;
    const int mblk = w & 1, h = w >> 1;

    const unsigned char* kim = g_kimg + (size_t)(b * 64) * 32768;
    const unsigned char* eim = g_eimg + (size_t)(b * 64) * 32768;

    // prologue loads: [Q + K0], [E0]
    load32k(sb + SQ, g_qimg + (size_t)(b * 64 + qt) * 32768, tid);
    load32k(sb + SK, kim, tid);
    CP_COMMIT();
    load32k(sb + SE, eim, tid);
    CP_COMMIT();

    // per-warp address bases
    const uint32_t qbase = (uint32_t)(mblk * 16384) + l * 16;      // + s*512
    const uint32_t kfoff = (uint32_t)(2 * h) * 256 + l * 8;        // + s*1024 + j*256
    const uint32_t efoff = (uint32_t)(16 * h) * 256 + l * 8;       // + s*8192 + ntl*256
    const uint32_t prow = (uint32_t)(mblk * 16 + gid);
    const uint32_t pbase = SP + (prow * 36 + tig) * 4;             // + 8s*4

    float yacc[16][4];
#pragma unroll
    for (int nt = 0; nt < 16; nt++)
#pragma unroll
        for (int j = 0; j < 4; j++) yacc[nt][j] = 0.f;
    float d0 = 0.f, d1 = 0.f;

    for (int t = 0; t < cnt; t++) {
        CP_WAIT1();                 // Q + K_t resident (E_t may be in flight)
        __syncthreads();

        // ---- S = Q K^T : warp -> S[16 rows @ 16mblk][16 cols @ 16h] ----
        float sacc[2][4];
#pragma unroll
        for (int j = 0; j < 2; j++)
#pragma unroll
            for (int i = 0; i < 4; i++) sacc[j][i] = 0.f;
#pragma unroll 4
        for (int s = 0; s < 32; s++) {
            uint32_t qa[4];
            *(uint4*)qa = *(const uint4*)(smp + SQ + qbase + (uint32_t)s * 512);
#pragma unroll
            for (int j = 0; j < 2; j++) {
                uint32_t kf[2];
                *(uint2*)kf = *(const uint2*)(smp + SK + (uint32_t)s * 1024 + kfoff + j * 256);
                mmat(sacc[j], qa, kf);
            }
        }
        __syncthreads();            // K buffer readers done
        if (t + 1 < cnt) load32k(sb + SK, kim + (size_t)(t + 1) * 32768, tid);
        CP_COMMIT();                // K_{t+1} (or empty) -- overlaps exp + AV

        // ---- exp/mask -> tf32 P (smem) + den ----
        {
            const int r0 = q0 + mblk * 16 + gid, r1 = r0 + 8;
            const int cb = t * 32 + 16 * h + 2 * tig;
#pragma unroll
            for (int j = 0; j < 2; j++) {
                int c0 = cb + 8 * j, c1 = c0 + 1;
                uint32_t t00, t01, t10, t11;
                if (t == cnt - 1) {   // diagonal tile: causal mask applies
                    t00 = tf32r((c0 <= r0) ? expclip(sacc[j][0]) : 0.f);
                    t01 = tf32r((c1 <= r0) ? expclip(sacc[j][1]) : 0.f);
                    t10 = tf32r((c0 <= r1) ? expclip(sacc[j][2]) : 0.f);
                    t11 = tf32r((c1 <= r1) ? expclip(sacc[j][3]) : 0.f);
                } else {
                    t00 = tf32r(expclip(sacc[j][0]));
                    t01 = tf32r(expclip(sacc[j][1]));
                    t10 = tf32r(expclip(sacc[j][2]));
                    t11 = tf32r(expclip(sacc[j][3]));
                }
                d0 += __uint_as_float(t00) + __uint_as_float(t01);
                d1 += __uint_as_float(t10) + __uint_as_float(t11);
                uint32_t a = SP + (prow * 36 + 16 * h + 8 * j + 2 * tig) * 4;
                *(uint2*)(smp + a) = make_uint2(t00, t01);
                *(uint2*)(smp + a + 8 * 36 * 4) = make_uint2(t10, t11);
            }
        }
        CP_WAIT1();                 // E_t resident (K_{t+1} still in flight)
        __syncthreads();            // P visible

        // ---- y += P E : warp -> y[16 rows][128 cols @ 128h] ----
#pragma unroll
        for (int s = 0; s < 4; s++) {
            uint32_t pa[4];
            uint32_t pb = pbase + (uint32_t)(8 * s) * 4;
            pa[0] = *(const uint32_t*)(smp + pb);
            pa[1] = *(const uint32_t*)(smp + pb + 8 * 36 * 4);
            pa[2] = *(const uint32_t*)(smp + pb + 16);
            pa[3] = *(const uint32_t*)(smp + pb + 8 * 36 * 4 + 16);
#pragma unroll
            for (int ntl = 0; ntl < 16; ntl++) {
                uint32_t ef[2];
                *(uint2*)ef = *(const uint2*)(smp + SE + (uint32_t)s * 8192 + efoff + ntl * 256);
                mmat(yacc[ntl], pa, ef);
            }
        }
        __syncthreads();            // E buffer readers done
        if (t + 1 < cnt) load32k(sb + SE, eim + (size_t)(t + 1) * 32768, tid);
        CP_COMMIT();                // E_{t+1} (or empty) -- overlaps next QK
    }

    // ---- den reduce ----
    d0 += __shfl_xor_sync(~0u, d0, 1); d0 += __shfl_xor_sync(~0u, d0, 2);
    d1 += __shfl_xor_sync(~0u, d1, 1); d1 += __shfl_xor_sync(~0u, d1, 2);
    if (tig == 0) {
        *(float*)(smp + SDEN + (h * 32 + mblk * 16 + gid) * 4) = d0;
        *(float*)(smp + SDEN + (h * 32 + mblk * 16 + gid + 8) * 4) = d1;
    }
    __syncthreads();
    float inv0, inv1;
    {
        const float* dn = (const float*)(smp + SDEN);
        int r = mblk * 16 + gid;
        inv0 = 1.f / ((dn[r] + dn[32 + r]) * (float)(q0 + r + 1));
        inv1 = 1.f / ((dn[r + 8] + dn[32 + r + 8]) * (float)(q0 + r + 9));
    }

    // start W pipeline into freed K/E buffers
    load32k(sb + SK, g_wimg, tid); CP_COMMIT();
    load32k(sb + SE, g_wimg + 32768, tid); CP_COMMIT();

    // ---- stage ynorm (tf32) into [32][260] over SQ+SP ----
#pragma unroll
    for (int ntl = 0; ntl < 16; ntl++) {
        uint32_t col = 128 * h + 8 * ntl + 2 * tig;
        uint32_t a = (prow * 260 + col) * 4;
        *(uint2*)(smp + a) = make_uint2(tf32r(yacc[ntl][0] * inv0), tf32r(yacc[ntl][1] * inv0));
        *(uint2*)(smp + a + 8 * 260 * 4) = make_uint2(tf32r(yacc[ntl][2] * inv1), tf32r(yacc[ntl][3] * inv1));
#pragma unroll
        for (int j = 0; j < 4; j++) yacc[ntl][j] = 0.f;
    }
    __syncthreads();                // ynorm visible

    // ---- epilogue: out = ynorm @ W2 (8 chunks of 32 j) ----
#pragma unroll 1
    for (int c = 0; c < 8; c++) {
        CP_WAIT1();
        __syncthreads();
        const uint32_t wb = (c & 1) ? SE : SK;
#pragma unroll
        for (int s = 0; s < 4; s++) {
            uint32_t ya[4];
            uint32_t yb = (prow * 260 + 32 * c + 8 * s + tig) * 4;
            ya[0] = *(const uint32_t*)(smp + yb);
            ya[1] = *(const uint32_t*)(smp + yb + 8 * 260 * 4);
            ya[2] = *(const uint32_t*)(smp + yb + 16);
            ya[3] = *(const uint32_t*)(smp + yb + 8 * 260 * 4 + 16);
#pragma unroll
            for (int ntl = 0; ntl < 16; ntl++) {
                uint32_t wf[2];
                *(uint2*)wf = *(const uint2*)(smp + wb + (uint32_t)s * 8192 + efoff + ntl * 256);
                mmat(yacc[ntl], ya, wf);
            }
        }
        __syncthreads();            // buffer readers done
        if (c + 2 < 8) load32k(sb + ((c & 1) ? SE : SK), g_wimg + (size_t)(c + 2) * 32768, tid);
        CP_COMMIT();                // real or empty group
    }

    // ---- store ----
    {
        const int orow = q0 + mblk * 16 + gid;
        float* ob = out + ((size_t)b * Ss + orow) * Dh;
#pragma unroll
        for (int ntl = 0; ntl < 16; ntl++) {
            int col = 128 * h + 8 * ntl + 2 * tig;
            *(float2*)(ob + col) = make_float2(yacc[ntl][0], yacc[ntl][1]);
            *(float2*)(ob + 8 * Dh + col) = make_float2(yacc[ntl][2], yacc[ntl][3]);
        }
    }
}

extern "C" void kernel_launch(void* const* d_in, const int* in_sizes, int n_in,
                              void* d_out, int out_size) {
    const float* e   = (const float*)d_in[0];
    const float* p   = (const float*)d_in[1];
    const float* W_o = (const float*)d_in[2];
    float* out = (float*)d_out;

    cudaFuncSetAttribute(attn_kernel, cudaFuncAttributeMaxDynamicSharedMemorySize, SMEM_BYTES);

    img_kernel<<<dim3(64, 8, 3), 256>>>(p, e);
    wimg_kernel<<<8, 256>>>(W_o);
    attn_kernel<<<dim3(64, 8), 128, SMEM_BYTES>>>(out);
}

// round 13
// speedup vs baseline: 1.4214x; 1.1701x over previous
#include <cuda_runtime.h>
#include <stdint.h>

#define Ss 2048
#define Dh 256

__device__ __align__(16) unsigned char g_qimg[8 * 64 * 32768];  // A-frag images, 32-row q-tiles
__device__ __align__(16) unsigned char g_kimg[8 * 64 * 32768];  // B-frag images, 32-key tiles
__device__ __align__(16) unsigned char g_eimg[8 * 64 * 32768];  // B-frag images, 32-key tiles
__device__ __align__(16) unsigned char g_wimg[8 * 32768];       // B-frag images, 32-j chunks

// ---------------- helpers ----------------
__device__ __forceinline__ uint32_t smem_u32(const void* p) {
    uint32_t a; asm("{.reg .u64 t; cvta.to.shared.u64 t,%1; cvt.u32.u64 %0,t;}" : "=r"(a) : "l"(p)); return a;
}
__device__ __forceinline__ uint32_t tf32r(float x) {
    uint32_t r; asm("cvt.rna.tf32.f32 %0,%1;" : "=r"(r) : "f"(x)); return r;
}
__device__ __forceinline__ void mmat(float* c, const uint32_t* a, const uint32_t* b) {
    asm volatile("mma.sync.aligned.m16n8k8.row.col.f32.tf32.tf32.f32 "
        "{%0,%1,%2,%3},{%4,%5,%6,%7},{%8,%9},{%0,%1,%2,%3};"
        : "+f"(c[0]), "+f"(c[1]), "+f"(c[2]), "+f"(c[3])
        : "r"(a[0]), "r"(a[1]), "r"(a[2]), "r"(a[3]), "r"(b[0]), "r"(b[1]));
}
__device__ __forceinline__ float expclip(float s) {
    return __expf(fminf(fmaxf(s * 0.0625f, -10.f), 10.f));
}
__device__ __forceinline__ void cpa16(uint32_t dst, const void* src) {
    asm volatile("cp.async.cg.shared.global [%0],[%1],16;" :: "r"(dst), "l"(src));
}
#define CP_COMMIT() asm volatile("cp.async.commit_group;" ::: "memory")
#define CP_WAIT1()  asm volatile("cp.async.wait_group 1;" ::: "memory")

__device__ __forceinline__ void load32k(uint32_t dst, const unsigned char* src, int tid) {
#pragma unroll
    for (int i = 0; i < 16; i++)
        cpa16(dst + (uint32_t)(tid + 128 * i) * 16, src + (size_t)(tid + 128 * i) * 16);
}

// ---------------- prologue kernels ----------------
// z=0: Q A-frag image; z=1: K B-frag image; z=2: E B-frag image
__global__ void img_kernel(const float* __restrict__ p, const float* __restrict__ e) {
    int t = blockIdx.x, b = blockIdx.y, z = blockIdx.z, tid = threadIdx.x;
    if (z == 0) {
        const float* P = p + (size_t)b * (Ss + 1) * Dh;
        uint4* dst = (uint4*)(g_qimg + (size_t)(b * 64 + t) * 32768);
#pragma unroll
        for (int it = 0; it < 8; it++) {
            int idx = tid + 256 * it;
            int mblk = idx >> 10, rem = idx & 1023, s = rem >> 5, l = rem & 31;
            int r = t * 32 + mblk * 16 + (l >> 2) + 1;   // +1: q = p[:,1:,:]
            int c = 8 * s + (l & 3);
            uint4 v;
            v.x = tf32r(P[(size_t)r * Dh + c]);
            v.y = tf32r(P[(size_t)(r + 8) * Dh + c]);
            v.z = tf32r(P[(size_t)r * Dh + c + 4]);
            v.w = tf32r(P[(size_t)(r + 8) * Dh + c + 4]);
            dst[idx] = v;
        }
    } else if (z == 1) {
        const float* P = p + (size_t)b * (Ss + 1) * Dh;
        uint2* dst = (uint2*)(g_kimg + (size_t)(b * 64 + t) * 32768);
#pragma unroll
        for (int it = 0; it < 16; it++) {
            int idx = tid + 256 * it;
            int s = idx >> 7, rem = idx & 127, nt = rem >> 5, l = rem & 31;
            int key = t * 32 + nt * 8 + (l >> 2);
            int d = 8 * s + (l & 3);
            dst[idx] = make_uint2(tf32r(P[(size_t)key * Dh + d]), tf32r(P[(size_t)key * Dh + d + 4]));
        }
    } else {
        const float* E = e + (size_t)b * Ss * Dh;
        uint2* dst = (uint2*)(g_eimg + (size_t)(b * 64 + t) * 32768);
#pragma unroll
        for (int it = 0; it < 16; it++) {
            int idx = tid + 256 * it;
            int s = idx >> 10, rem = idx & 1023, nt = rem >> 5, l = rem & 31;
            int key = t * 32 + 8 * s + (l & 3);
            int n = nt * 8 + (l >> 2);
            dst[idx] = make_uint2(tf32r(E[(size_t)key * Dh + n]), tf32r(E[(size_t)(key + 4) * Dh + n]));
        }
    }
}
// W image straight from W_o (fold 8 heads inline): element (j, n=dout)
__global__ void wimg_kernel(const float* __restrict__ W_o) {
    int ch = blockIdx.x, tid = threadIdx.x;
    uint2* dst = (uint2*)(g_wimg + (size_t)ch * 32768);
#pragma unroll
    for (int it = 0; it < 16; it++) {
        int idx = tid + 256 * it;
        int s = idx >> 10, rem = idx & 1023, nt = rem >> 5, l = rem & 31;
        int j = 32 * ch + 8 * s + (l & 3);
        int n = nt * 8 + (l >> 2);
        float s0 = 0.f, s1 = 0.f;
#pragma unroll
        for (int h = 0; h < 8; h++) {
            s0 += W_o[(size_t)n * 2048 + h * 256 + j];
            s1 += W_o[(size_t)n * 2048 + h * 256 + j + 4];
        }
        dst[idx] = make_uint2(tf32r(s0), tf32r(s1));
    }
}

// ---------------- main kernel ----------------
// smem layout (bytes); ynorm [32][260] f32 (33280) lives at offset 0 (unused in k-loop)
#define SP   33280u    // P [32 rows][36 f32] = 4608
#define SK   37888u    // K tile image, 32768
#define SE   70656u    // E tile image, 32768
#define SDEN 103424u   // [2][32] f32
#define SMEM_BYTES 103680u

__global__ __launch_bounds__(128, 2) void attn_kernel(float* __restrict__ out) {
    extern __shared__ unsigned char smp[];
    const uint32_t sb = smem_u32(smp);
    const int tid = threadIdx.x, w = tid >> 5, l = tid & 31;
    const int tig = l & 3, gid = l >> 2;
    const int qt = 63 - (int)blockIdx.x, b = blockIdx.y;
    const int q0 = qt * 32, cnt = qt + 1;
    const int mblk = w & 1, h = w >> 1;

    const unsigned char* kim = g_kimg + (size_t)(b * 64) * 32768;
    const unsigned char* eim = g_eimg + (size_t)(b * 64) * 32768;

    // prologue cp.async: [K0], [E0]
    load32k(sb + SK, kim, tid);
    CP_COMMIT();
    load32k(sb + SE, eim, tid);
    CP_COMMIT();

    // ---- Q fragments -> registers (coalesced LDG from fragment image) ----
    uint32_t qr[32][4];
    {
        const uint4* qsrc = (const uint4*)(g_qimg + (size_t)(b * 64 + qt) * 32768)
                            + (uint32_t)(mblk * 1024) + l;
#pragma unroll
        for (int s = 0; s < 32; s++)
            *(uint4*)qr[s] = qsrc[s * 32];
    }

    // per-warp address bases
    const uint32_t kfoff = (uint32_t)(2 * h) * 256 + l * 8;        // + s*1024 + j*256
    const uint32_t efoff = (uint32_t)(16 * h) * 256 + l * 8;       // + s*8192 + ntl*256
    const uint32_t prow = (uint32_t)(mblk * 16 + gid);
    const uint32_t pbase = SP + (prow * 36 + tig) * 4;             // + 8s*4

    float yacc[16][4];
#pragma unroll
    for (int nt = 0; nt < 16; nt++)
#pragma unroll
        for (int j = 0; j < 4; j++) yacc[nt][j] = 0.f;
    float d0 = 0.f, d1 = 0.f;

    for (int t = 0; t < cnt; t++) {
        CP_WAIT1();                 // K_t resident (E_t may be in flight)
        __syncthreads();

        // ---- S = Q K^T : warp -> S[16 rows @ 16mblk][16 cols @ 16h] ----
        float sacc[2][4];
#pragma unroll
        for (int j = 0; j < 2; j++)
#pragma unroll
            for (int i = 0; i < 4; i++) sacc[j][i] = 0.f;
#pragma unroll
        for (int s = 0; s < 32; s++) {
#pragma unroll
            for (int j = 0; j < 2; j++) {
                uint32_t kf[2];
                *(uint2*)kf = *(const uint2*)(smp + SK + (uint32_t)s * 1024 + kfoff + j * 256);
                mmat(sacc[j], qr[s], kf);
            }
        }
        __syncthreads();            // K buffer readers done
        if (t + 1 < cnt) load32k(sb + SK, kim + (size_t)(t + 1) * 32768, tid);
        CP_COMMIT();                // K_{t+1} (or empty) -- overlaps exp + AV

        // ---- exp/mask -> tf32 P (smem) + den ----
        {
            const int r0 = q0 + mblk * 16 + gid, r1 = r0 + 8;
            const int cb = t * 32 + 16 * h + 2 * tig;
#pragma unroll
            for (int j = 0; j < 2; j++) {
                int c0 = cb + 8 * j, c1 = c0 + 1;
                uint32_t t00, t01, t10, t11;
                if (t == cnt - 1) {   // diagonal tile: causal mask applies
                    t00 = tf32r((c0 <= r0) ? expclip(sacc[j][0]) : 0.f);
                    t01 = tf32r((c1 <= r0) ? expclip(sacc[j][1]) : 0.f);
                    t10 = tf32r((c0 <= r1) ? expclip(sacc[j][2]) : 0.f);
                    t11 = tf32r((c1 <= r1) ? expclip(sacc[j][3]) : 0.f);
                } else {
                    t00 = tf32r(expclip(sacc[j][0]));
                    t01 = tf32r(expclip(sacc[j][1]));
                    t10 = tf32r(expclip(sacc[j][2]));
                    t11 = tf32r(expclip(sacc[j][3]));
                }
                d0 += __uint_as_float(t00) + __uint_as_float(t01);
                d1 += __uint_as_float(t10) + __uint_as_float(t11);
                uint32_t a = SP + (prow * 36 + 16 * h + 8 * j + 2 * tig) * 4;
                *(uint2*)(smp + a) = make_uint2(t00, t01);
                *(uint2*)(smp + a + 8 * 36 * 4) = make_uint2(t10, t11);
            }
        }
        CP_WAIT1();                 // E_t resident (K_{t+1} still in flight)
        __syncthreads();            // P visible

        // ---- y += P E : warp -> y[16 rows][128 cols @ 128h] ----
#pragma unroll
        for (int s = 0; s < 4; s++) {
            uint32_t pa[4];
            uint32_t pb = pbase + (uint32_t)(8 * s) * 4;
            pa[0] = *(const uint32_t*)(smp + pb);
            pa[1] = *(const uint32_t*)(smp + pb + 8 * 36 * 4);
            pa[2] = *(const uint32_t*)(smp + pb + 16);
            pa[3] = *(const uint32_t*)(smp + pb + 8 * 36 * 4 + 16);
#pragma unroll
            for (int ntl = 0; ntl < 16; ntl++) {
                uint32_t ef[2];
                *(uint2*)ef = *(const uint2*)(smp + SE + (uint32_t)s * 8192 + efoff + ntl * 256);
                mmat(yacc[ntl], pa, ef);
            }
        }
        __syncthreads();            // E buffer readers done
        if (t + 1 < cnt) load32k(sb + SE, eim + (size_t)(t + 1) * 32768, tid);
        CP_COMMIT();                // E_{t+1} (or empty) -- overlaps next QK
    }

    // ---- den reduce ----
    d0 += __shfl_xor_sync(~0u, d0, 1); d0 += __shfl_xor_sync(~0u, d0, 2);
    d1 += __shfl_xor_sync(~0u, d1, 1); d1 += __shfl_xor_sync(~0u, d1, 2);
    if (tig == 0) {
        *(float*)(smp + SDEN + (h * 32 + mblk * 16 + gid) * 4) = d0;
        *(float*)(smp + SDEN + (h * 32 + mblk * 16 + gid + 8) * 4) = d1;
    }
    __syncthreads();
    float inv0, inv1;
    {
        const float* dn = (const float*)(smp + SDEN);
        int r = mblk * 16 + gid;
        inv0 = 1.f / ((dn[r] + dn[32 + r]) * (float)(q0 + r + 1));
        inv1 = 1.f / ((dn[r + 8] + dn[32 + r + 8]) * (float)(q0 + r + 9));
    }

    // start W pipeline into freed K/E buffers
    load32k(sb + SK, g_wimg, tid); CP_COMMIT();
    load32k(sb + SE, g_wimg + 32768, tid); CP_COMMIT();

    // ---- stage ynorm (tf32) into [32][260] at smem offset 0 ----
#pragma unroll
    for (int ntl = 0; ntl < 16; ntl++) {
        uint32_t col = 128 * h + 8 * ntl + 2 * tig;
        uint32_t a = (prow * 260 + col) * 4;
        *(uint2*)(smp + a) = make_uint2(tf32r(yacc[ntl][0] * inv0), tf32r(yacc[ntl][1] * inv0));
        *(uint2*)(smp + a + 8 * 260 * 4) = make_uint2(tf32r(yacc[ntl][2] * inv1), tf32r(yacc[ntl][3] * inv1));
#pragma unroll
        for (int j = 0; j < 4; j++) yacc[ntl][j] = 0.f;
    }
    __syncthreads();                // ynorm visible

    // ---- epilogue: out = ynorm @ W2 (8 chunks of 32 j) ----
#pragma unroll 1
    for (int c = 0; c < 8; c++) {
        CP_WAIT1();
        __syncthreads();
        const uint32_t wb = (c & 1) ? SE : SK;
#pragma unroll
        for (int s = 0; s < 4; s++) {
            uint32_t ya[4];
            uint32_t yb = (prow * 260 + 32 * c + 8 * s + tig) * 4;
            ya[0] = *(const uint32_t*)(smp + yb);
            ya[1] = *(const uint32_t*)(smp + yb + 8 * 260 * 4);
            ya[2] = *(const uint32_t*)(smp + yb + 16);
            ya[3] = *(const uint32_t*)(smp + yb + 8 * 260 * 4 + 16);
#pragma unroll
            for (int ntl = 0; ntl < 16; ntl++) {
                uint32_t wf[2];
                *(uint2*)wf = *(const uint2*)(smp + wb + (uint32_t)s * 8192 + efoff + ntl * 256);
                mmat(yacc[ntl], ya, wf);
            }
        }
        __syncthreads();            // buffer readers done
        if (c + 2 < 8) load32k(sb + ((c & 1) ? SE : SK), g_wimg + (size_t)(c + 2) * 32768, tid);
        CP_COMMIT();                // real or empty group
    }

    // ---- store ----
    {
        const int orow = q0 + mblk * 16 + gid;
        float* ob = out + ((size_t)b * Ss + orow) * Dh;
#pragma unroll
        for (int ntl = 0; ntl < 16; ntl++) {
            int col = 128 * h + 8 * ntl + 2 * tig;
            *(float2*)(ob + col) = make_float2(yacc[ntl][0], yacc[ntl][1]);
            *(float2*)(ob + 8 * Dh + col) = make_float2(yacc[ntl][2], yacc[ntl][3]);
        }
    }
}

extern "C" void kernel_launch(void* const* d_in, const int* in_sizes, int n_in,
                              void* d_out, int out_size) {
    const float* e   = (const float*)d_in[0];
    const float* p   = (const float*)d_in[1];
    const float* W_o = (const float*)d_in[2];
    float* out = (float*)d_out;

    cudaFuncSetAttribute(attn_kernel, cudaFuncAttributeMaxDynamicSharedMemorySize, SMEM_BYTES);

    img_kernel<<<dim3(64, 8, 3), 256>>>(p, e);
    wimg_kernel<<<8, 256>>>(W_o);
    attn_kernel<<<dim3(64, 8), 128, SMEM_BYTES>>>(out);
}

// round 14
// speedup vs baseline: 1.6227x; 1.1416x over previous
#include <cuda_runtime.h>
#include <stdint.h>

#define Ss 2048
#define Dh 256

__device__ __align__(16) unsigned char g_qimg[8 * 64 * 16384];  // fp16 A-frag images, 32-row q-tiles
__device__ __align__(16) unsigned char g_kimg[8 * 64 * 16384];  // fp16 B-frag images, 32-key tiles
__device__ __align__(16) unsigned char g_eimg[8 * 64 * 16384];  // fp16 B-frag images, 32-key tiles
__device__ __align__(16) unsigned char g_wimg[8 * 16384];       // fp16 B-frag images, 32-j chunks

// ---------------- helpers ----------------
__device__ __forceinline__ uint32_t smem_u32(const void* p) {
    uint32_t a; asm("{.reg .u64 t; cvta.to.shared.u64 t,%1; cvt.u32.u64 %0,t;}" : "=r"(a) : "l"(p)); return a;
}
__device__ __forceinline__ uint32_t tf32r(float x) {
    uint32_t r; asm("cvt.rna.tf32.f32 %0,%1;" : "=r"(r) : "f"(x)); return r;
}
__device__ __forceinline__ uint32_t hpk(float a, float b) {   // pack: lo=a, hi=b
    uint32_t r; asm("cvt.rn.f16x2.f32 %0,%2,%1;" : "=r"(r) : "f"(a), "f"(b)); return r;
}
__device__ __forceinline__ void hup(uint32_t u, uint32_t* o) { // unpack fp16x2 -> 2 f32 (exact)
    float a, b;
    asm("{.reg .f16 l,h; mov.b32 {l,h},%2; cvt.f32.f16 %0,l; cvt.f32.f16 %1,h;}"
        : "=f"(a), "=f"(b) : "r"(u));
    o[0] = __float_as_uint(a); o[1] = __float_as_uint(b);
}
__device__ __forceinline__ void mmat(float* c, const uint32_t* a, const uint32_t* b) {
    asm volatile("mma.sync.aligned.m16n8k8.row.col.f32.tf32.tf32.f32 "
        "{%0,%1,%2,%3},{%4,%5,%6,%7},{%8,%9},{%0,%1,%2,%3};"
        : "+f"(c[0]), "+f"(c[1]), "+f"(c[2]), "+f"(c[3])
        : "r"(a[0]), "r"(a[1]), "r"(a[2]), "r"(a[3]), "r"(b[0]), "r"(b[1]));
}
__device__ __forceinline__ float expclip(float s) {
    return __expf(fminf(fmaxf(s * 0.0625f, -10.f), 10.f));
}
__device__ __forceinline__ void cpa16(uint32_t dst, const void* src) {
    asm volatile("cp.async.cg.shared.global [%0],[%1],16;" :: "r"(dst), "l"(src));
}
#define CP_COMMIT() asm volatile("cp.async.commit_group;" ::: "memory")
#define CP_WAIT1()  asm volatile("cp.async.wait_group 1;" ::: "memory")
#define CP_WAIT3()  asm volatile("cp.async.wait_group 3;" ::: "memory")

__device__ __forceinline__ void load16k(uint32_t dst, const unsigned char* src, int tid) {
#pragma unroll
    for (int i = 0; i < 8; i++)
        cpa16(dst + (uint32_t)(tid + 128 * i) * 16, src + (size_t)(tid + 128 * i) * 16);
}

// ---------------- prologue kernels ----------------
// z=0: Q A-frag image; z=1: K B-frag image; z=2: E B-frag image   (all fp16)
__global__ void img_kernel(const float* __restrict__ p, const float* __restrict__ e) {
    int t = blockIdx.x, b = blockIdx.y, z = blockIdx.z, tid = threadIdx.x;
    if (z == 0) {
        const float* P = p + (size_t)b * (Ss + 1) * Dh;
        uint2* dst = (uint2*)(g_qimg + (size_t)(b * 64 + t) * 16384);
#pragma unroll
        for (int it = 0; it < 8; it++) {
            int idx = tid + 256 * it;
            if (idx >= 2048) break;
            int mblk = idx >> 10, rem = idx & 1023, s = rem >> 5, l = rem & 31;
            int r = t * 32 + mblk * 16 + (l >> 2) + 1;   // +1: q = p[:,1:,:]
            int c = 8 * s + (l & 3);
            dst[idx] = make_uint2(
                hpk(P[(size_t)r * Dh + c],     P[(size_t)(r + 8) * Dh + c]),
                hpk(P[(size_t)r * Dh + c + 4], P[(size_t)(r + 8) * Dh + c + 4]));
        }
    } else if (z == 1) {
        const float* P = p + (size_t)b * (Ss + 1) * Dh;
        uint32_t* dst = (uint32_t*)(g_kimg + (size_t)(b * 64 + t) * 16384);
#pragma unroll
        for (int it = 0; it < 16; it++) {
            int idx = tid + 256 * it;
            int s = idx >> 7, rem = idx & 127, nt = rem >> 5, l = rem & 31;
            int key = t * 32 + nt * 8 + (l >> 2);
            int d = 8 * s + (l & 3);
            dst[idx] = hpk(P[(size_t)key * Dh + d], P[(size_t)key * Dh + d + 4]);
        }
    } else {
        const float* E = e + (size_t)b * Ss * Dh;
        uint32_t* dst = (uint32_t*)(g_eimg + (size_t)(b * 64 + t) * 16384);
#pragma unroll
        for (int it = 0; it < 16; it++) {
            int idx = tid + 256 * it;
            int s = idx >> 10, rem = idx & 1023, nt = rem >> 5, l = rem & 31;
            int key = t * 32 + 8 * s + (l & 3);
            int n = nt * 8 + (l >> 2);
            dst[idx] = hpk(E[(size_t)key * Dh + n], E[(size_t)(key + 4) * Dh + n]);
        }
    }
}
// W image from W_o (fold 8 heads inline): element (j, n=dout), fp16
__global__ void wimg_kernel(const float* __restrict__ W_o) {
    int ch = blockIdx.x, tid = threadIdx.x;
    uint32_t* dst = (uint32_t*)(g_wimg + (size_t)ch * 16384);
#pragma unroll
    for (int it = 0; it < 16; it++) {
        int idx = tid + 256 * it;
        int s = idx >> 10, rem = idx & 1023, nt = rem >> 5, l = rem & 31;
        int j = 32 * ch + 8 * s + (l & 3);
        int n = nt * 8 + (l >> 2);
        float s0 = 0.f, s1 = 0.f;
#pragma unroll
        for (int h = 0; h < 8; h++) {
            s0 += W_o[(size_t)n * 2048 + h * 256 + j];
            s1 += W_o[(size_t)n * 2048 + h * 256 + j + 4];
        }
        dst[idx] = hpk(s0, s1);
    }
}

// ---------------- main kernel ----------------
// smem (bytes): ynorm [32][260] f32 (33280) at 0 (epilogue only)
#define SP   33280u    // P [32 rows][36 f32] = 4608
#define SK0  37888u    // K buffers (fp16, 16KB each)
#define SK1  54272u
#define SE0  70656u    // E buffers
#define SE1  87040u
#define SDEN 103424u   // [2][32] f32
#define SMEM_BYTES 103680u

__global__ __launch_bounds__(128, 2) void attn_kernel(float* __restrict__ out) {
    extern __shared__ unsigned char smp[];
    const uint32_t sb = smem_u32(smp);
    const int tid = threadIdx.x, w = tid >> 5, l = tid & 31;
    const int tig = l & 3, gid = l >> 2;
    const int qt = 63 - (int)blockIdx.x, b = blockIdx.y;
    const int q0 = qt * 32, cnt = qt + 1;
    const int mblk = w & 1, h = w >> 1;

    const unsigned char* kim = g_kimg + (size_t)(b * 64) * 16384;
    const unsigned char* eim = g_eimg + (size_t)(b * 64) * 16384;

    // prologue: group0 = [K0+E0], group1 = [K1+E1] (or empty)
    load16k(sb + SK0, kim, tid);
    load16k(sb + SE0, eim, tid);
    CP_COMMIT();
    if (cnt > 1) {
        load16k(sb + SK1, kim + 16384, tid);
        load16k(sb + SE1, eim + 16384, tid);
    }
    CP_COMMIT();

    // ---- Q fragments -> registers (fp16 image, exact widen to tf32) ----
    uint32_t qr[32][4];
    {
        const uint2* qsrc = (const uint2*)(g_qimg + (size_t)(b * 64 + qt) * 16384)
                            + (uint32_t)(mblk * 1024) + l;
#pragma unroll
        for (int s = 0; s < 32; s++) {
            uint2 v = qsrc[s * 32];
            hup(v.x, &qr[s][0]);
            hup(v.y, &qr[s][2]);
        }
    }

    // per-warp address components
    const uint32_t kfq = (uint32_t)(2 * h) * 128 + l * 4;     // + s*512 + j*128
    const uint32_t efh = (uint32_t)h * 2048 + l * 4;          // + s*4096 + ntl*128
    const uint32_t prow = (uint32_t)(mblk * 16 + gid);
    const uint32_t pbase = SP + (prow * 36 + tig) * 4;        // + 8s*4

    float yacc[16][4];
#pragma unroll
    for (int nt = 0; nt < 16; nt++)
#pragma unroll
        for (int j = 0; j < 4; j++) yacc[nt][j] = 0.f;
    float d0 = 0.f, d1 = 0.f;

    for (int t = 0; t < cnt; t++) {
        const uint32_t kb = (t & 1) ? SK1 : SK0;
        const uint32_t eb = (t & 1) ? SE1 : SE0;
        CP_WAIT1();                 // K_t/E_t resident (t+1 group may be in flight)
        __syncthreads();            // + all warps done with these buffers' previous use

        // ---- S = Q K^T : warp -> S[16 rows @ 16mblk][16 cols @ 16h] ----
        float sacc[2][4];
#pragma unroll
        for (int j = 0; j < 2; j++)
#pragma unroll
            for (int i = 0; i < 4; i++) sacc[j][i] = 0.f;
#pragma unroll
        for (int s = 0; s < 32; s++) {
#pragma unroll
            for (int j = 0; j < 2; j++) {
                uint32_t kf[2];
                hup(*(const uint32_t*)(smp + kb + (uint32_t)s * 512 + kfq + j * 128), kf);
                mmat(sacc[j], qr[s], kf);
            }
        }

        // ---- exp/mask -> tf32 P (smem) + den ----
        {
            const int r0 = q0 + mblk * 16 + gid, r1 = r0 + 8;
            const int cb = t * 32 + 16 * h + 2 * tig;
#pragma unroll
            for (int j = 0; j < 2; j++) {
                int c0 = cb + 8 * j, c1 = c0 + 1;
                uint32_t t00, t01, t10, t11;
                if (t == cnt - 1) {   // diagonal tile: causal mask applies
                    t00 = tf32r((c0 <= r0) ? expclip(sacc[j][0]) : 0.f);
                    t01 = tf32r((c1 <= r0) ? expclip(sacc[j][1]) : 0.f);
                    t10 = tf32r((c0 <= r1) ? expclip(sacc[j][2]) : 0.f);
                    t11 = tf32r((c1 <= r1) ? expclip(sacc[j][3]) : 0.f);
                } else {
                    t00 = tf32r(expclip(sacc[j][0]));
                    t01 = tf32r(expclip(sacc[j][1]));
                    t10 = tf32r(expclip(sacc[j][2]));
                    t11 = tf32r(expclip(sacc[j][3]));
                }
                d0 += __uint_as_float(t00) + __uint_as_float(t01);
                d1 += __uint_as_float(t10) + __uint_as_float(t11);
                uint32_t a = SP + (prow * 36 + 16 * h + 8 * j + 2 * tig) * 4;
                *(uint2*)(smp + a) = make_uint2(t00, t01);
                *(uint2*)(smp + a + 8 * 36 * 4) = make_uint2(t10, t11);
            }
        }
        __syncthreads();            // P visible (E_t already resident from the tile-top wait)

        // ---- y += P E : warp -> y[16 rows][128 cols @ 128h] ----
#pragma unroll
        for (int s = 0; s < 4; s++) {
            uint32_t pa[4];
            uint32_t pb = pbase + (uint32_t)(8 * s) * 4;
            pa[0] = *(const uint32_t*)(smp + pb);
            pa[1] = *(const uint32_t*)(smp + pb + 8 * 36 * 4);
            pa[2] = *(const uint32_t*)(smp + pb + 16);
            pa[3] = *(const uint32_t*)(smp + pb + 8 * 36 * 4 + 16);
#pragma unroll
            for (int ntl = 0; ntl < 16; ntl++) {
                uint32_t ef[2];
                hup(*(const uint32_t*)(smp + eb + (uint32_t)s * 4096 + efh + ntl * 128), ef);
                mmat(yacc[ntl], pa, ef);
            }
        }
        __syncthreads();            // all warps done reading K_t/E_t (and P)
        if (t + 2 < cnt) {          // refill the just-used buffers for tile t+2
            load16k(sb + kb, kim + (size_t)(t + 2) * 16384, tid);
            load16k(sb + eb, eim + (size_t)(t + 2) * 16384, tid);
        }
        CP_COMMIT();                // real or empty group
    }

    // ---- den reduce ----
    d0 += __shfl_xor_sync(~0u, d0, 1); d0 += __shfl_xor_sync(~0u, d0, 2);
    d1 += __shfl_xor_sync(~0u, d1, 1); d1 += __shfl_xor_sync(~0u, d1, 2);
    if (tig == 0) {
        *(float*)(smp + SDEN + (h * 32 + mblk * 16 + gid) * 4) = d0;
        *(float*)(smp + SDEN + (h * 32 + mblk * 16 + gid + 8) * 4) = d1;
    }
    __syncthreads();
    float inv0, inv1;
    {
        const float* dn = (const float*)(smp + SDEN);
        int r = mblk * 16 + gid;
        inv0 = 1.f / ((dn[r] + dn[32 + r]) * (float)(q0 + r + 1));
        inv1 = 1.f / ((dn[r + 8] + dn[32 + r + 8]) * (float)(q0 + r + 9));
    }

    // start W pipeline into the 4 freed buffers (4 groups)
    load16k(sb + SK0, g_wimg, tid); CP_COMMIT();
    load16k(sb + SE0, g_wimg + 16384, tid); CP_COMMIT();
    load16k(sb + SK1, g_wimg + 2 * 16384, tid); CP_COMMIT();
    load16k(sb + SE1, g_wimg + 3 * 16384, tid); CP_COMMIT();

    // ---- stage ynorm (tf32) into [32][260] at smem offset 0 ----
#pragma unroll
    for (int ntl = 0; ntl < 16; ntl++) {
        uint32_t col = 128 * h + 8 * ntl + 2 * tig;
        uint32_t a = (prow * 260 + col) * 4;
        *(uint2*)(smp + a) = make_uint2(tf32r(yacc[ntl][0] * inv0), tf32r(yacc[ntl][1] * inv0));
        *(uint2*)(smp + a + 8 * 260 * 4) = make_uint2(tf32r(yacc[ntl][2] * inv1), tf32r(yacc[ntl][3] * inv1));
#pragma unroll
        for (int j = 0; j < 4; j++) yacc[ntl][j] = 0.f;
    }
    __syncthreads();                // ynorm visible

    // ---- epilogue: out = ynorm @ W2 (8 chunks of 32 j, 4 rotating buffers) ----
#pragma unroll 1
    for (int c = 0; c < 8; c++) {
        CP_WAIT3();                 // W_c resident
        __syncthreads();
        const uint32_t wbl[4] = { SK0, SE0, SK1, SE1 };
        const uint32_t wb = wbl[c & 3];
#pragma unroll
        for (int s = 0; s < 4; s++) {
            uint32_t ya[4];
            uint32_t yb = (prow * 260 + 32 * c + 8 * s + tig) * 4;
            ya[0] = *(const uint32_t*)(smp + yb);
            ya[1] = *(const uint32_t*)(smp + yb + 8 * 260 * 4);
            ya[2] = *(const uint32_t*)(smp + yb + 16);
            ya[3] = *(const uint32_t*)(smp + yb + 8 * 260 * 4 + 16);
#pragma unroll
            for (int ntl = 0; ntl < 16; ntl++) {
                uint32_t wf[2];
                hup(*(const uint32_t*)(smp + wb + (uint32_t)s * 4096 + efh + ntl * 128), wf);
                mmat(yacc[ntl], ya, wf);
            }
        }
        __syncthreads();            // buffer readers done
        if (c + 4 < 8) load16k(sb + wb, g_wimg + (size_t)(c + 4) * 16384, tid);
        CP_COMMIT();                // real or empty group
    }

    // ---- store ----
    {
        const int orow = q0 + mblk * 16 + gid;
        float* ob = out + ((size_t)b * Ss + orow) * Dh;
#pragma unroll
        for (int ntl = 0; ntl < 16; ntl++) {
            int col = 128 * h + 8 * ntl + 2 * tig;
            *(float2*)(ob + col) = make_float2(yacc[ntl][0], yacc[ntl][1]);
            *(float2*)(ob + 8 * Dh + col) = make_float2(yacc[ntl][2], yacc[ntl][3]);
        }
    }
}

extern "C" void kernel_launch(void* const* d_in, const int* in_sizes, int n_in,
                              void* d_out, int out_size) {
    const float* e   = (const float*)d_in[0];
    const float* p   = (const float*)d_in[1];
    const float* W_o = (const float*)d_in[2];
    float* out = (float*)d_out;

    cudaFuncSetAttribute(attn_kernel, cudaFuncAttributeMaxDynamicSharedMemorySize, SMEM_BYTES);

    img_kernel<<<dim3(64, 8, 3), 256>>>(p, e);
    wimg_kernel<<<8, 256>>>(W_o);
    attn_kernel<<<dim3(64, 8), 128, SMEM_BYTES>>>(out);
}